// round 4
// baseline (speedup 1.0000x reference)
#include <cuda_runtime.h>

// DeformableCONV: modulated deformable conv v2, depthwise (groups = C).
// x:       (B, C, H, W)           f32
// offsets: (B, 2*C*KK, H, W)      f32   layout (B, C, KK, 2{dy,dx}, H, W)
// mask:    (B, C*KK, H, W)        f32   layout (B, C, KK, H, W)
// weight:  (C, 1, K, K)           f32
// bias:    (C,)                   f32
// out:     (B, C, H, W)           f32

#define B_ 32
#define C_ 17
#define H_ 96
#define W_ 72
#define KK_ 9
#define HW_ (H_ * W_)           // 6912
#define NTHREADS 256

__global__ __launch_bounds__(NTHREADS)
void dcn_kernel(const float* __restrict__ x,
                const float* __restrict__ off,
                const float* __restrict__ mask,
                const float* __restrict__ weight,
                const float* __restrict__ bias,
                float* __restrict__ out)
{
    __shared__ float sx[HW_];   // one (b,c) input plane: 27,648 B

    const int bc = blockIdx.x;          // b * C_ + c
    const int c  = bc % C_;
    const int b  = bc / C_;
    const int tid = threadIdx.x;

    // Stage x plane into shared (single coalesced pass over HBM/L2).
    const float* __restrict__ xp = x + (size_t)bc * HW_;
    #pragma unroll
    for (int i = tid; i < HW_; i += NTHREADS)
        sx[i] = xp[i];

    // Per-channel weights + bias into registers (broadcast via L1).
    float wk[KK_];
    #pragma unroll
    for (int k = 0; k < KK_; ++k)
        wk[k] = weight[c * KK_ + k];
    const float bv = bias[c];

    __syncthreads();

    const float* __restrict__ offb = off  + (size_t)b * (2 * C_ * KK_ * HW_)
                                          + (size_t)(c * KK_) * 2 * HW_;
    const float* __restrict__ mb   = mask + (size_t)b * (C_ * KK_ * HW_)
                                          + (size_t)(c * KK_) * HW_;
    float* __restrict__ op = out + (size_t)bc * HW_;

    // 6912 / 256 = 27 pixels per thread, coalesced across the warp.
    for (int p = tid; p < HW_; p += NTHREADS) {
        const int h = p / W_;
        const int w = p - h * W_;

        float acc = 0.0f;

        #pragma unroll
        for (int k = 0; k < KK_; ++k) {
            const float dy = offb[(2 * k    ) * HW_ + p];
            const float dx = offb[(2 * k + 1) * HW_ + p];
            const float m  = mb[k * HW_ + p];

            const int ky = k / 3;
            const int kx = k - ky * 3;

            const float py = (float)(h - 1 + ky) + dy;
            const float px = (float)(w - 1 + kx) + dx;

            const float y0f = floorf(py);
            const float x0f = floorf(px);
            const int y0 = (int)y0f;
            const int x0 = (int)x0f;
            const float wy = py - y0f;
            const float wx = px - x0f;
            const int y1 = y0 + 1;
            const int x1 = x0 + 1;

            const bool vy0 = (y0 >= 0) & (y0 < H_);
            const bool vy1 = (y1 >= 0) & (y1 < H_);
            const bool vx0 = (x0 >= 0) & (x0 < W_);
            const bool vx1 = (x1 >= 0) & (x1 < W_);

            // Clamp indices for safe smem access; validity zeroes the weight
            // (matches reference: value clamped, weight gated).
            const int cy0 = min(max(y0, 0), H_ - 1);
            const int cy1 = min(max(y1, 0), H_ - 1);
            const int cx0 = min(max(x0, 0), W_ - 1);
            const int cx1 = min(max(x1, 0), W_ - 1);

            float v = 0.0f;
            if (vy0 & vx0) v += sx[cy0 * W_ + cx0] * (1.0f - wy) * (1.0f - wx);
            if (vy0 & vx1) v += sx[cy0 * W_ + cx1] * (1.0f - wy) * wx;
            if (vy1 & vx0) v += sx[cy1 * W_ + cx0] * wy * (1.0f - wx);
            if (vy1 & vx1) v += sx[cy1 * W_ + cx1] * wy * wx;

            acc = fmaf(m * v, wk[k], acc);
        }

        op[p] = acc + bv;
    }
}

extern "C" void kernel_launch(void* const* d_in, const int* in_sizes, int n_in,
                              void* d_out, int out_size)
{
    const float* x      = (const float*)d_in[0];
    const float* off    = (const float*)d_in[1];
    const float* mask   = (const float*)d_in[2];
    const float* weight = (const float*)d_in[3];
    const float* bias   = (const float*)d_in[4];
    float* out          = (float*)d_out;

    dcn_kernel<<<B_ * C_, NTHREADS>>>(x, off, mask, weight, bias, out);
}

// round 5
// speedup vs baseline: 1.6658x; 1.6658x over previous
#include <cuda_runtime.h>

// DeformableCONV: modulated deformable conv v2, depthwise (groups = C).
// x:       (B, C, H, W)           f32
// offsets: (B, 2*C*KK, H, W)      f32   layout (B, C, KK, 2{dy,dx}, H, W)
// mask:    (B, C*KK, H, W)        f32   layout (B, C, KK, H, W)
// weight:  (C, 1, K, K)           f32
// bias:    (C,)                   f32
// out:     (B, C, H, W)           f32

#define B_ 32
#define C_ 17
#define H_ 96
#define W_ 72
#define KK_ 9
#define HW_ (H_ * W_)           // 6912
#define NTHREADS 256
#define SPLIT 3
#define PIX_PER (HW_ / SPLIT)   // 2304 = 9 * 256, exact

__global__ __launch_bounds__(NTHREADS, 6)
void dcn_kernel(const float* __restrict__ x,
                const float* __restrict__ off,
                const float* __restrict__ mask,
                const float* __restrict__ weight,
                const float* __restrict__ bias,
                float* __restrict__ out)
{
    __shared__ float sx[HW_];   // one (b,c) input plane: 27,648 B

    const int s  = blockIdx.x;          // plane split index 0..SPLIT-1
    const int bc = blockIdx.y;          // b * C_ + c
    const int c  = bc % C_;
    const int b  = bc / C_;
    const int tid = threadIdx.x;

    // Stage full x plane into shared. Sibling CTAs (same bc, different s)
    // launch adjacently -> 2nd/3rd reads hit L2, DRAM reads x once.
    const float* __restrict__ xp = x + (size_t)bc * HW_;
    #pragma unroll
    for (int i = tid; i < HW_; i += NTHREADS)
        sx[i] = xp[i];

    float wk[KK_];
    #pragma unroll
    for (int k = 0; k < KK_; ++k)
        wk[k] = weight[c * KK_ + k];
    const float bv = bias[c];

    __syncthreads();

    const float* __restrict__ offb = off  + (size_t)b * (2 * C_ * KK_ * HW_)
                                          + (size_t)(c * KK_) * 2 * HW_;
    const float* __restrict__ mb   = mask + (size_t)b * (C_ * KK_ * HW_)
                                          + (size_t)(c * KK_) * HW_;
    float* __restrict__ op = out + (size_t)bc * HW_;

    const int p0   = s * PIX_PER + tid;
    const int pend = (s + 1) * PIX_PER;

    // Incremental h/w tracking: stride 256 = 3*72 + 40.
    int h = p0 / W_;
    int w = p0 - h * W_;

    for (int p = p0; p < pend; p += NTHREADS) {
        float acc = 0.0f;

        #pragma unroll
        for (int k = 0; k < KK_; ++k) {
            const float dy = offb[(2 * k    ) * HW_ + p];
            const float dx = offb[(2 * k + 1) * HW_ + p];
            const float m  = mb[k * HW_ + p];

            const int ky = k / 3;
            const int kx = k - ky * 3;

            const float py = (float)(h - 1 + ky) + dy;
            const float px = (float)(w - 1 + kx) + dx;

            const float y0f = floorf(py);
            const float x0f = floorf(px);
            const int y0 = (int)y0f;
            const int x0 = (int)x0f;
            const float wy = py - y0f;
            const float wx = px - x0f;
            const float iwy = 1.0f - wy;
            const float iwx = 1.0f - wx;
            const int y1 = y0 + 1;
            const int x1 = x0 + 1;

            const bool vy0 = (unsigned)y0 < (unsigned)H_;
            const bool vy1 = (unsigned)y1 < (unsigned)H_;
            const bool vx0 = (unsigned)x0 < (unsigned)W_;
            const bool vx1 = (unsigned)x1 < (unsigned)W_;

            const int cy0 = min(max(y0, 0), H_ - 1);
            const int cy1 = min(max(y1, 0), H_ - 1);
            const int cx0 = min(max(x0, 0), W_ - 1);
            const int cx1 = min(max(x1, 0), W_ - 1);

            float v = 0.0f;
            if (vy0 & vx0) v = fmaf(sx[cy0 * W_ + cx0], iwy * iwx, v);
            if (vy0 & vx1) v = fmaf(sx[cy0 * W_ + cx1], iwy * wx,  v);
            if (vy1 & vx0) v = fmaf(sx[cy1 * W_ + cx0], wy  * iwx, v);
            if (vy1 & vx1) v = fmaf(sx[cy1 * W_ + cx1], wy  * wx,  v);

            acc = fmaf(m * v, wk[k], acc);
        }

        op[p] = acc + bv;

        // advance (h, w) by 256 pixels: 256 = 3*W_ + 40
        h += 3; w += 40;
        if (w >= W_) { w -= W_; ++h; }
    }
}

extern "C" void kernel_launch(void* const* d_in, const int* in_sizes, int n_in,
                              void* d_out, int out_size)
{
    const float* x      = (const float*)d_in[0];
    const float* off    = (const float*)d_in[1];
    const float* mask   = (const float*)d_in[2];
    const float* weight = (const float*)d_in[3];
    const float* bias   = (const float*)d_in[4];
    float* out          = (float*)d_out;

    dim3 grid(SPLIT, B_ * C_);
    dcn_kernel<<<grid, NTHREADS>>>(x, off, mask, weight, bias, out);
}

// round 7
// speedup vs baseline: 1.8284x; 1.0976x over previous
#include <cuda_runtime.h>

// DeformableCONV: modulated deformable conv v2, depthwise (groups = C).
// x:       (B, C, H, W)           f32
// offsets: (B, 2*C*KK, H, W)      f32   layout (B, C, KK, 2{dy,dx}, H, W)
// mask:    (B, C*KK, H, W)        f32   layout (B, C, KK, H, W)
// weight:  (C, 1, K, K)           f32
// bias:    (C,)                   f32
// out:     (B, C, H, W)           f32

#define B_ 32
#define C_ 17
#define H_ 96
#define W_ 72
#define KK_ 9
#define HW_ (H_ * W_)           // 6912
#define NTHREADS 256
#define SPLIT 3
#define PIX_PER (HW_ / SPLIT)   // 2304, even
#define PW (W_ + 3)             // 75: col 0 zero, cols 1..72 data, 73,74 zero
#define PH (H_ + 3)             // 99: row 0 zero, rows 1..96 data, 97,98 zero

// Branchless bilinear gather from zero-padded smem plane.
// Clamping py to [-1, H] / px to [-1, W] is exact: at/beyond the clamp every
// real texel's interpolation weight is 0 and padding reads 0.
__device__ __forceinline__ float bilerp(const float* __restrict__ sx,
                                        float py, float px)
{
    py = fminf(fmaxf(py, -1.0f), (float)H_);
    px = fminf(fmaxf(px, -1.0f), (float)W_);
    const float y0f = floorf(py);
    const float x0f = floorf(px);
    const float wy = py - y0f;
    const float wx = px - x0f;
    const int idx = ((int)y0f + 1) * PW + ((int)x0f + 1);
    const float s00 = sx[idx];
    const float s01 = sx[idx + 1];
    const float s10 = sx[idx + PW];
    const float s11 = sx[idx + PW + 1];
    const float vt = fmaf(wx, s01 - s00, s00);
    const float vb = fmaf(wx, s11 - s10, s10);
    return fmaf(wy, vb - vt, vt);
}

__global__ __launch_bounds__(NTHREADS, 6)
void dcn_kernel(const float* __restrict__ x,
                const float* __restrict__ off,
                const float* __restrict__ mask,
                const float* __restrict__ weight,
                const float* __restrict__ bias,
                float* __restrict__ out)
{
    __shared__ float sx[PH * PW];       // 29,700 B zero-padded (b,c) plane

    const int s  = blockIdx.x;          // plane split index 0..SPLIT-1
    const int bc = blockIdx.y;          // b * C_ + c
    const int c  = bc % C_;
    const int b  = bc / C_;
    const int tid = threadIdx.x;

    // Zero the padded plane, then fill interior. Sibling CTAs (same bc,
    // different s) are adjacent in the grid -> x plane hits L2 after 1st read.
    #pragma unroll
    for (int i = tid; i < PH * PW; i += NTHREADS)
        sx[i] = 0.0f;

    float wk[KK_];
    #pragma unroll
    for (int k = 0; k < KK_; ++k)
        wk[k] = weight[c * KK_ + k];
    const float bv = bias[c];

    __syncthreads();

    const float* __restrict__ xp = x + (size_t)bc * HW_;
    #pragma unroll
    for (int i = tid; i < HW_; i += NTHREADS) {
        const int r = i / W_;
        const int cc = i - r * W_;
        sx[(r + 1) * PW + (cc + 1)] = xp[i];
    }
    __syncthreads();

    const float* __restrict__ offb = off  + (size_t)b * (2 * C_ * KK_ * HW_)
                                          + (size_t)(c * KK_) * 2 * HW_;
    const float* __restrict__ mb   = mask + (size_t)b * (C_ * KK_ * HW_)
                                          + (size_t)(c * KK_) * HW_;
    float* __restrict__ op = out + (size_t)bc * HW_;

    // Each thread handles pixel pairs (p, p+1), p even. Since W_ is even and
    // the stride (2*NTHREADS) is even, the pair never wraps a row.
    const int p0   = s * PIX_PER + tid * 2;
    const int pend = (s + 1) * PIX_PER;

    int h = p0 / W_;
    int w = p0 - h * W_;
    // stride 512 = 7*72 + 8
    for (int p = p0; p < pend; p += 2 * NTHREADS) {
        float acc0 = 0.0f, acc1 = 0.0f;

        const float hy = (float)(h - 1);
        const float wx0 = (float)(w - 1);
        const float wx1 = (float)w;

        #pragma unroll
        for (int k = 0; k < KK_; ++k) {
            const float2 dy = __ldcs((const float2*)(offb + (size_t)(2 * k    ) * HW_ + p));
            const float2 dx = __ldcs((const float2*)(offb + (size_t)(2 * k + 1) * HW_ + p));
            const float2 m  = __ldcs((const float2*)(mb   + (size_t)k           * HW_ + p));

            const int ky = k / 3;
            const int kx = k - ky * 3;

            const float v0 = bilerp(sx, hy + (float)ky + dy.x, wx0 + (float)kx + dx.x);
            const float v1 = bilerp(sx, hy + (float)ky + dy.y, wx1 + (float)kx + dx.y);

            acc0 = fmaf(m.x * v0, wk[k], acc0);
            acc1 = fmaf(m.y * v1, wk[k], acc1);
        }

        __stcs((float2*)(op + p), make_float2(acc0 + bv, acc1 + bv));

        // advance (h, w) by 512 pixels: 512 = 7*W_ + 8
        h += 7; w += 8;
        if (w >= W_) { w -= W_; ++h; }
    }
}

extern "C" void kernel_launch(void* const* d_in, const int* in_sizes, int n_in,
                              void* d_out, int out_size)
{
    const float* x      = (const float*)d_in[0];
    const float* off    = (const float*)d_in[1];
    const float* mask   = (const float*)d_in[2];
    const float* weight = (const float*)d_in[3];
    const float* bias   = (const float*)d_in[4];
    float* out          = (float*)d_out;

    dim3 grid(SPLIT, B_ * C_);
    dcn_kernel<<<grid, NTHREADS>>>(x, off, mask, weight, bias, out);
}